// round 15
// baseline (speedup 1.0000x reference)
#include <cuda_runtime.h>
#include <math.h>

// SparseMixerMoeRoutingMethod: top-2 routing over 64 experts, sparse-mixer mask.
//
// Validated core (R9/R14): 4 lanes/token, 8 tokens/warp, chunk-interleaved
// ownership (lane sub owns float4 chunks {4k+sub}; expert gj = 16k+4sub+r,
// composed as disjoint bitfields: gj = ((j&12)<<2) | (sub<<2) | (j&3)).
//
//   A) tournament top-2 (log-depth sorted-pair merge tree) + 2-step group
//      reduce -> m1, m2.
//      keep <=> (m-x) <= 0.2*max(|x|,m) <=> x >= m*(m>0 ? 0.8 : 1.25) (exact)
//   B) 16-bit candidate mask of x >= thr2 (superset of both kept sets);
//      row registers die here (gather reloads via __ldg, L1-hot).
//   C) sparse gather (~0.6 bits/lane): e = ex2((x-m1)*log2e);
//      s1 = sum_{x>=thr1} e -> sel1 = 1/s1;
//      s2 = sum_{x>=thr2} e -> sel2 = ex2((m2-m1)*log2e)/(s2-1).
//   D) fused 2-step shfl reduction {s1,s2,mi1,mi2}; rare m1==m2 tie fallback.
//
// R15 change: 512-thread blocks (4096 blocks instead of 16384) — same
// occupancy arithmetic (2048 thr/SM), 4x less CTA launch/drain overhead.
//
// Output: single fp32 buffer, [indices-as-float (2n) | values (2n)].

#define NUM_EXPERTS 64
#define L2E 1.4426950408889634f

__device__ __forceinline__ float ex2(float t) {
    float r;
    asm("ex2.approx.ftz.f32 %0, %1;" : "=f"(r) : "f"(t));
    return r;
}
__device__ __forceinline__ float rcp(float t) {
    float r;
    asm("rcp.approx.ftz.f32 %0, %1;" : "=f"(r) : "f"(t));
    return r;
}

// Merge two sorted pairs -> sorted top-2 of the union.
#define MERGE2(H, L, h1v, l1v, h2v, l2v)                 \
    do {                                                 \
        H = fmaxf(h1v, h2v);                             \
        L = fmaxf(fminf(h1v, h2v), fmaxf(l1v, l2v));     \
    } while (0)

template <bool FULL>
__global__ void __launch_bounds__(512, 4)
sparse_mixer_routing_kernel(const float* __restrict__ logits,
                            float* __restrict__ out,
                            int n_tokens) {
    const int warp  = (blockIdx.x * blockDim.x + threadIdx.x) >> 5;
    const int lane  = threadIdx.x & 31;
    const int grp   = lane >> 2;          // 8 token-groups of 4 lanes
    const int sub   = lane & 3;
    const int token = warp * 8 + grp;
    const int tok_c = FULL ? token : min(token, n_tokens - 1);

    const float* rowp = logits + (size_t)tok_c * NUM_EXPERTS;
    const int lane_off = sub << 2;        // bits [2:3]

    float m1, m2;
    unsigned mask = 0;
    {
        const float4* r4 = reinterpret_cast<const float4*>(rowp);
        const float4 v0 = r4[sub];
        const float4 v1 = r4[4 + sub];
        const float4 v2 = r4[8 + sub];
        const float4 v3 = r4[12 + sub];
        const float xs[16] = {v0.x, v0.y, v0.z, v0.w, v1.x, v1.y, v1.z, v1.w,
                              v2.x, v2.y, v2.z, v2.w, v3.x, v3.y, v3.z, v3.w};

        // ---- A: tournament top-2 (log-depth) ----
        float h[8], l[8];
        #pragma unroll
        for (int p = 0; p < 8; ++p) {      // 8 independent sorted pairs
            h[p] = fmaxf(xs[2*p], xs[2*p+1]);
            l[p] = fminf(xs[2*p], xs[2*p+1]);
        }
        float H0,L0,H1,L1,H2,L2,H3,L3;
        MERGE2(H0, L0, h[0], l[0], h[1], l[1]);
        MERGE2(H1, L1, h[2], l[2], h[3], l[3]);
        MERGE2(H2, L2, h[4], l[4], h[5], l[5]);
        MERGE2(H3, L3, h[6], l[6], h[7], l[7]);
        float HA,LA,HB,LB;
        MERGE2(HA, LA, H0, L0, H1, L1);
        MERGE2(HB, LB, H2, L2, H3, L3);
        MERGE2(m1, m2, HA, LA, HB, LB);

        // 4-lane group top-2 reduction (xor 2,1 stay in-group)
        #pragma unroll
        for (int off = 2; off > 0; off >>= 1) {
            const float om1 = __shfl_xor_sync(0xffffffffu, m1, off);
            const float om2 = __shfl_xor_sync(0xffffffffu, m2, off);
            m2 = fmaxf(fmaxf(m2, om2), fminf(m1, om1));
            m1 = fmaxf(m1, om1);
        }

        // ---- B: candidate mask (x >= thr2; thr2 <= thr1) ----
        const float t2 = m2 * (m2 > 0.0f ? 0.8f : 1.25f);
        #pragma unroll
        for (int j = 0; j < 16; ++j)
            if (xs[j] >= t2) mask |= (1u << j);
        // row registers dead here (gather + fallback reload via __ldg).
    }

    const float thr1 = m1 * (m1 > 0.0f ? 0.8f : 1.25f);
    const float c1   = -m1 * L2E;

    // ---- C: sparse gather ----
    float s1 = 0.0f, s2 = 0.0f;
    int mi1 = 127, mi2 = 127;
    while (mask) {
        const int j = __ffs(mask) - 1;
        mask &= mask - 1;
        // disjoint bitfields: (j&12)<<2 -> bits[4:5], lane_off -> [2:3], j&3 -> [0:1]
        const int gj = ((j & 12) << 2) | lane_off | (j & 3);
        const float v = __ldg(rowp + gj);    // L1 hit (row just loaded)
        const float e = ex2(fmaf(v, L2E, c1));
        s2 += e;
        if (v >= thr1) s1 += e;
        if (v == m1) mi1 = min(mi1, gj);
        if (v == m2) mi2 = min(mi2, gj);
    }

    // ---- D: fused group reduction: sums + index mins ----
    #pragma unroll
    for (int off = 2; off > 0; off >>= 1) {
        s1 += __shfl_xor_sync(0xffffffffu, s1, off);
        s2 += __shfl_xor_sync(0xffffffffu, s2, off);
        mi1 = min(mi1, __shfl_xor_sync(0xffffffffu, mi1, off));
        mi2 = min(mi2, __shfl_xor_sync(0xffffffffu, mi2, off));
    }

    // ---- rare exact-tie fallback: m1 == m2 -> lowest m2-pos excluding mi1 ----
    if (__ballot_sync(0xffffffffu, m1 == m2)) {
        int sec = 127;
        #pragma unroll
        for (int j = 0; j < 16; ++j) {
            const int gj = ((j & 12) << 2) | lane_off | (j & 3);
            const float v = __ldg(rowp + gj);   // L1-hot
            if (v == m2 && gj != mi1) sec = min(sec, gj);
        }
        #pragma unroll
        for (int off = 2; off > 0; off >>= 1)
            sec = min(sec, __shfl_xor_sync(0xffffffffu, sec, off));
        if (m1 == m2) mi2 = sec;
    }

    if (sub == 0 && (FULL || token < n_tokens)) {
        const float sel1 = rcp(s1);
        const float sel2 = ex2(fmaf(m2, L2E, c1)) * rcp(s2 - 1.0f);
        reinterpret_cast<float2*>(out)[token] =
            make_float2((float)mi1, (float)mi2);
        reinterpret_cast<float2*>(out + 2 * (size_t)n_tokens)[token] =
            make_float2(sel1, sel2);
    }
}

extern "C" void kernel_launch(void* const* d_in, const int* in_sizes, int n_in,
                              void* d_out, int out_size) {
    const float* logits = (const float*)d_in[0];
    const int n_tokens  = in_sizes[0] / NUM_EXPERTS;

    float* out = (float*)d_out;

    const int threads = 512;                 // 16 warps = 128 tokens/block
    const int tokens_per_block = (threads / 32) * 8;

    if ((n_tokens % tokens_per_block) == 0) {
        const int blocks = n_tokens / tokens_per_block;
        sparse_mixer_routing_kernel<true><<<blocks, threads>>>(logits, out,
                                                               n_tokens);
    } else {
        const int blocks = (n_tokens + tokens_per_block - 1) / tokens_per_block;
        sparse_mixer_routing_kernel<false><<<blocks, threads>>>(logits, out,
                                                                n_tokens);
    }
}

// round 16
// speedup vs baseline: 1.0011x; 1.0011x over previous
#include <cuda_runtime.h>
#include <math.h>

// SparseMixerMoeRoutingMethod: top-2 routing over 64 experts, sparse-mixer mask.
// CONVERGED configuration (best measured: 29.12us, ~5.4 TB/s effective).
//
// Layout: 4 lanes/token, 8 tokens/warp, 128-thread blocks, chunk-interleaved
// ownership: lane sub owns float4 chunks {4k+sub}; expert index composes as
// disjoint bitfields gj = ((j&12)<<2) | (sub<<2) | (j&3). Each LDG.128
// covers a contiguous 64B band of 8 consecutive rows (full sector use).
//
//   A) tournament top-2 (log-depth sorted-pair merge tree, ~44 FMNMX,
//      ~6-level chain) + 2-step 4-lane group reduce -> m1, m2
//      (m2 == pass-2 max after masking the argmax position; multiset top-2).
//      keep <=> (m-x) <= 0.2*max(|x|,m) <=> x >= m*(m>0 ? 0.8 : 1.25) (exact)
//   B) 16-bit candidate mask of x >= thr2 (superset of both passes' kept
//      sets; contains the m1/m2 positions). Row registers die here.
//   C) sparse gather over set bits (~0.6 avg/lane): reload via __ldg
//      (L1-hot); m1-relative exp e = ex2((x-m1)*log2e) serves both passes:
//        s1 = sum_{x>=thr1} e  -> sel1 = 1/s1
//        s2 = sum_{x>=thr2} e  -> sel2 = ex2((m2-m1)*log2e)/(s2 - 1)
//      (m1 term contributes exactly ~1 to s2; subtracting removes it, and
//       this stays correct under exact m1==m2 ties.)
//      Index matches tracked as global-index mins in the same loop.
//   D) fused 2-step shfl reduction {s1, s2, mi1, mi2}.
//   Rare exact m1==m2 tie: ballot-guarded fallback rescan (L1-hot) for the
//   lowest m2 position excluding mi1 (jnp.argmax first-occurrence semantics).
//
// Output: single fp32 buffer, [indices-as-float (2n) | values (2n)].

#define NUM_EXPERTS 64
#define L2E 1.4426950408889634f

__device__ __forceinline__ float ex2(float t) {
    float r;
    asm("ex2.approx.ftz.f32 %0, %1;" : "=f"(r) : "f"(t));
    return r;
}
__device__ __forceinline__ float rcp(float t) {
    float r;
    asm("rcp.approx.ftz.f32 %0, %1;" : "=f"(r) : "f"(t));
    return r;
}

// Merge two sorted pairs -> sorted top-2 of the union.
#define MERGE2(H, L, h1v, l1v, h2v, l2v)                 \
    do {                                                 \
        H = fmaxf(h1v, h2v);                             \
        L = fmaxf(fminf(h1v, h2v), fmaxf(l1v, l2v));     \
    } while (0)

template <bool FULL>
__global__ void __launch_bounds__(128, 16)
sparse_mixer_routing_kernel(const float* __restrict__ logits,
                            float* __restrict__ out,
                            int n_tokens) {
    const int warp  = (blockIdx.x * blockDim.x + threadIdx.x) >> 5;
    const int lane  = threadIdx.x & 31;
    const int grp   = lane >> 2;          // 8 token-groups of 4 lanes
    const int sub   = lane & 3;
    const int token = warp * 8 + grp;
    const int tok_c = FULL ? token : min(token, n_tokens - 1);

    const float* rowp = logits + (size_t)tok_c * NUM_EXPERTS;
    const int lane_off = sub << 2;        // bits [2:3] of the expert index

    float m1, m2;
    unsigned mask = 0;
    {
        const float4* r4 = reinterpret_cast<const float4*>(rowp);
        const float4 v0 = r4[sub];
        const float4 v1 = r4[4 + sub];
        const float4 v2 = r4[8 + sub];
        const float4 v3 = r4[12 + sub];
        const float xs[16] = {v0.x, v0.y, v0.z, v0.w, v1.x, v1.y, v1.z, v1.w,
                              v2.x, v2.y, v2.z, v2.w, v3.x, v3.y, v3.z, v3.w};

        // ---- A: tournament top-2 (log-depth) ----
        float h[8], l[8];
        #pragma unroll
        for (int p = 0; p < 8; ++p) {      // 8 independent sorted pairs
            h[p] = fmaxf(xs[2*p], xs[2*p+1]);
            l[p] = fminf(xs[2*p], xs[2*p+1]);
        }
        float H0,L0,H1,L1,H2,L2,H3,L3;
        MERGE2(H0, L0, h[0], l[0], h[1], l[1]);
        MERGE2(H1, L1, h[2], l[2], h[3], l[3]);
        MERGE2(H2, L2, h[4], l[4], h[5], l[5]);
        MERGE2(H3, L3, h[6], l[6], h[7], l[7]);
        float HA,LA,HB,LB;
        MERGE2(HA, LA, H0, L0, H1, L1);
        MERGE2(HB, LB, H2, L2, H3, L3);
        MERGE2(m1, m2, HA, LA, HB, LB);

        // 4-lane group top-2 reduction (xor 2,1 stay in-group)
        #pragma unroll
        for (int off = 2; off > 0; off >>= 1) {
            const float om1 = __shfl_xor_sync(0xffffffffu, m1, off);
            const float om2 = __shfl_xor_sync(0xffffffffu, m2, off);
            m2 = fmaxf(fmaxf(m2, om2), fminf(m1, om1));
            m1 = fmaxf(m1, om1);
        }

        // ---- B: candidate mask (x >= thr2; thr2 <= thr1) ----
        const float t2 = m2 * (m2 > 0.0f ? 0.8f : 1.25f);
        #pragma unroll
        for (int j = 0; j < 16; ++j)
            if (xs[j] >= t2) mask |= (1u << j);
        // row registers dead here (gather + fallback reload via __ldg).
    }

    const float thr1 = m1 * (m1 > 0.0f ? 0.8f : 1.25f);
    const float c1   = -m1 * L2E;

    // ---- C: sparse gather ----
    float s1 = 0.0f, s2 = 0.0f;
    int mi1 = 127, mi2 = 127;
    while (mask) {
        const int j = __ffs(mask) - 1;
        mask &= mask - 1;
        // disjoint bitfields: (j&12)<<2 -> [4:5], lane_off -> [2:3], j&3 -> [0:1]
        const int gj = ((j & 12) << 2) | lane_off | (j & 3);
        const float v = __ldg(rowp + gj);    // L1 hit (row just loaded)
        const float e = ex2(fmaf(v, L2E, c1));
        s2 += e;
        if (v >= thr1) s1 += e;
        if (v == m1) mi1 = min(mi1, gj);
        if (v == m2) mi2 = min(mi2, gj);
    }

    // ---- D: fused group reduction: sums + index mins ----
    #pragma unroll
    for (int off = 2; off > 0; off >>= 1) {
        s1 += __shfl_xor_sync(0xffffffffu, s1, off);
        s2 += __shfl_xor_sync(0xffffffffu, s2, off);
        mi1 = min(mi1, __shfl_xor_sync(0xffffffffu, mi1, off));
        mi2 = min(mi2, __shfl_xor_sync(0xffffffffu, mi2, off));
    }

    // ---- rare exact-tie fallback: m1 == m2 -> lowest m2-pos excluding mi1 ----
    if (__ballot_sync(0xffffffffu, m1 == m2)) {
        int sec = 127;
        #pragma unroll
        for (int j = 0; j < 16; ++j) {
            const int gj = ((j & 12) << 2) | lane_off | (j & 3);
            const float v = __ldg(rowp + gj);   // L1-hot
            if (v == m2 && gj != mi1) sec = min(sec, gj);
        }
        #pragma unroll
        for (int off = 2; off > 0; off >>= 1)
            sec = min(sec, __shfl_xor_sync(0xffffffffu, sec, off));
        if (m1 == m2) mi2 = sec;
    }

    if (sub == 0 && (FULL || token < n_tokens)) {
        const float sel1 = rcp(s1);
        const float sel2 = ex2(fmaf(m2, L2E, c1)) * rcp(s2 - 1.0f);
        reinterpret_cast<float2*>(out)[token] =
            make_float2((float)mi1, (float)mi2);
        reinterpret_cast<float2*>(out + 2 * (size_t)n_tokens)[token] =
            make_float2(sel1, sel2);
    }
}

extern "C" void kernel_launch(void* const* d_in, const int* in_sizes, int n_in,
                              void* d_out, int out_size) {
    const float* logits = (const float*)d_in[0];
    const int n_tokens  = in_sizes[0] / NUM_EXPERTS;

    float* out = (float*)d_out;

    const int threads = 128;                 // 4 warps = 32 tokens/block
    const int tokens_per_block = (threads / 32) * 8;

    if ((n_tokens & 7) == 0) {
        const int blocks = n_tokens / tokens_per_block;
        sparse_mixer_routing_kernel<true><<<blocks, threads>>>(logits, out,
                                                               n_tokens);
    } else {
        const int blocks = (n_tokens + tokens_per_block - 1) / tokens_per_block;
        sparse_mixer_routing_kernel<false><<<blocks, threads>>>(logits, out,
                                                                n_tokens);
    }
}

// round 17
// speedup vs baseline: 1.0033x; 1.0022x over previous
#include <cuda_runtime.h>
#include <math.h>

// SparseMixerMoeRoutingMethod: top-2 routing over 64 experts, sparse-mixer mask.
// FINAL converged configuration (29.12-29.18us across R11-R16; ~5.4 TB/s).
//
// Layout: 4 lanes/token, 8 tokens/warp, 128-thread blocks, chunk-interleaved
// ownership: lane sub owns float4 chunks {4k+sub}; expert index composes as
// disjoint bitfields gj = ((j&12)<<2) | (sub<<2) | (j&3). Each LDG.128
// covers a contiguous 64B band of 8 consecutive rows (full sector use).
//
//   A) tournament top-2 (log-depth sorted-pair merge tree, ~44 FMNMX,
//      ~6-level chain) + 2-step 4-lane group reduce -> m1, m2
//      (m2 == pass-2 max after masking the argmax position; multiset top-2).
//      keep <=> (m-x) <= 0.2*max(|x|,m) <=> x >= m*(m>0 ? 0.8 : 1.25) (exact)
//   B) 16-bit candidate mask of x >= thr2 (superset of both passes' kept
//      sets; contains the m1/m2 positions). Row registers die here.
//   C) sparse gather over set bits (~0.6 avg/lane): reload via __ldg
//      (L1-hot); m1-relative exp e = ex2((x-m1)*log2e) serves both passes:
//        s1 = sum_{x>=thr1} e  -> sel1 = 1/s1
//        s2 = sum_{x>=thr2} e  -> sel2 = ex2((m2-m1)*log2e)/(s2 - 1)
//      (m1 term contributes exactly ~1 to s2; subtracting removes it, and
//       this stays correct under exact m1==m2 ties.)
//      Index matches tracked as global-index mins in the same loop.
//   D) fused 2-step shfl reduction {s1, s2, mi1, mi2}.
//   Rare exact m1==m2 tie: ballot-guarded fallback rescan (L1-hot) for the
//   lowest m2 position excluding mi1 (jnp.argmax first-occurrence semantics).
//
// Output: single fp32 buffer, [indices-as-float (2n) | values (2n)].

#define NUM_EXPERTS 64
#define L2E 1.4426950408889634f

__device__ __forceinline__ float ex2(float t) {
    float r;
    asm("ex2.approx.ftz.f32 %0, %1;" : "=f"(r) : "f"(t));
    return r;
}
__device__ __forceinline__ float rcp(float t) {
    float r;
    asm("rcp.approx.ftz.f32 %0, %1;" : "=f"(r) : "f"(t));
    return r;
}

// Merge two sorted pairs -> sorted top-2 of the union.
#define MERGE2(H, L, h1v, l1v, h2v, l2v)                 \
    do {                                                 \
        H = fmaxf(h1v, h2v);                             \
        L = fmaxf(fminf(h1v, h2v), fmaxf(l1v, l2v));     \
    } while (0)

template <bool FULL>
__global__ void __launch_bounds__(128, 16)
sparse_mixer_routing_kernel(const float* __restrict__ logits,
                            float* __restrict__ out,
                            int n_tokens) {
    const int warp  = (blockIdx.x * blockDim.x + threadIdx.x) >> 5;
    const int lane  = threadIdx.x & 31;
    const int grp   = lane >> 2;          // 8 token-groups of 4 lanes
    const int sub   = lane & 3;
    const int token = warp * 8 + grp;
    const int tok_c = FULL ? token : min(token, n_tokens - 1);

    const float* rowp = logits + (size_t)tok_c * NUM_EXPERTS;
    const int lane_off = sub << 2;        // bits [2:3] of the expert index

    float m1, m2;
    unsigned mask = 0;
    {
        const float4* r4 = reinterpret_cast<const float4*>(rowp);
        const float4 v0 = r4[sub];
        const float4 v1 = r4[4 + sub];
        const float4 v2 = r4[8 + sub];
        const float4 v3 = r4[12 + sub];
        const float xs[16] = {v0.x, v0.y, v0.z, v0.w, v1.x, v1.y, v1.z, v1.w,
                              v2.x, v2.y, v2.z, v2.w, v3.x, v3.y, v3.z, v3.w};

        // ---- A: tournament top-2 (log-depth) ----
        float h[8], l[8];
        #pragma unroll
        for (int p = 0; p < 8; ++p) {      // 8 independent sorted pairs
            h[p] = fmaxf(xs[2*p], xs[2*p+1]);
            l[p] = fminf(xs[2*p], xs[2*p+1]);
        }
        float H0,L0,H1,L1,H2,L2,H3,L3;
        MERGE2(H0, L0, h[0], l[0], h[1], l[1]);
        MERGE2(H1, L1, h[2], l[2], h[3], l[3]);
        MERGE2(H2, L2, h[4], l[4], h[5], l[5]);
        MERGE2(H3, L3, h[6], l[6], h[7], l[7]);
        float HA,LA,HB,LB;
        MERGE2(HA, LA, H0, L0, H1, L1);
        MERGE2(HB, LB, H2, L2, H3, L3);
        MERGE2(m1, m2, HA, LA, HB, LB);

        // 4-lane group top-2 reduction (xor 2,1 stay in-group)
        #pragma unroll
        for (int off = 2; off > 0; off >>= 1) {
            const float om1 = __shfl_xor_sync(0xffffffffu, m1, off);
            const float om2 = __shfl_xor_sync(0xffffffffu, m2, off);
            m2 = fmaxf(fmaxf(m2, om2), fminf(m1, om1));
            m1 = fmaxf(m1, om1);
        }

        // ---- B: candidate mask (x >= thr2; thr2 <= thr1) ----
        const float t2 = m2 * (m2 > 0.0f ? 0.8f : 1.25f);
        #pragma unroll
        for (int j = 0; j < 16; ++j)
            if (xs[j] >= t2) mask |= (1u << j);
        // row registers dead here (gather + fallback reload via __ldg).
    }

    const float thr1 = m1 * (m1 > 0.0f ? 0.8f : 1.25f);
    const float c1   = -m1 * L2E;

    // ---- C: sparse gather ----
    float s1 = 0.0f, s2 = 0.0f;
    int mi1 = 127, mi2 = 127;
    while (mask) {
        const int j = __ffs(mask) - 1;
        mask &= mask - 1;
        // disjoint bitfields: (j&12)<<2 -> [4:5], lane_off -> [2:3], j&3 -> [0:1]
        const int gj = ((j & 12) << 2) | lane_off | (j & 3);
        const float v = __ldg(rowp + gj);    // L1 hit (row just loaded)
        const float e = ex2(fmaf(v, L2E, c1));
        s2 += e;
        if (v >= thr1) s1 += e;
        if (v == m1) mi1 = min(mi1, gj);
        if (v == m2) mi2 = min(mi2, gj);
    }

    // ---- D: fused group reduction: sums + index mins ----
    #pragma unroll
    for (int off = 2; off > 0; off >>= 1) {
        s1 += __shfl_xor_sync(0xffffffffu, s1, off);
        s2 += __shfl_xor_sync(0xffffffffu, s2, off);
        mi1 = min(mi1, __shfl_xor_sync(0xffffffffu, mi1, off));
        mi2 = min(mi2, __shfl_xor_sync(0xffffffffu, mi2, off));
    }

    // ---- rare exact-tie fallback: m1 == m2 -> lowest m2-pos excluding mi1 ----
    if (__ballot_sync(0xffffffffu, m1 == m2)) {
        int sec = 127;
        #pragma unroll
        for (int j = 0; j < 16; ++j) {
            const int gj = ((j & 12) << 2) | lane_off | (j & 3);
            const float v = __ldg(rowp + gj);   // L1-hot
            if (v == m2 && gj != mi1) sec = min(sec, gj);
        }
        #pragma unroll
        for (int off = 2; off > 0; off >>= 1)
            sec = min(sec, __shfl_xor_sync(0xffffffffu, sec, off));
        if (m1 == m2) mi2 = sec;
    }

    if (sub == 0 && (FULL || token < n_tokens)) {
        const float sel1 = rcp(s1);
        const float sel2 = ex2(fmaf(m2, L2E, c1)) * rcp(s2 - 1.0f);
        reinterpret_cast<float2*>(out)[token] =
            make_float2((float)mi1, (float)mi2);
        reinterpret_cast<float2*>(out + 2 * (size_t)n_tokens)[token] =
            make_float2(sel1, sel2);
    }
}

extern "C" void kernel_launch(void* const* d_in, const int* in_sizes, int n_in,
                              void* d_out, int out_size) {
    const float* logits = (const float*)d_in[0];
    const int n_tokens  = in_sizes[0] / NUM_EXPERTS;

    float* out = (float*)d_out;

    const int threads = 128;                 // 4 warps = 32 tokens/block
    const int tokens_per_block = (threads / 32) * 8;

    if ((n_tokens & 7) == 0) {
        const int blocks = n_tokens / tokens_per_block;
        sparse_mixer_routing_kernel<true><<<blocks, threads>>>(logits, out,
                                                               n_tokens);
    } else {
        const int blocks = (n_tokens + tokens_per_block - 1) / tokens_per_block;
        sparse_mixer_routing_kernel<false><<<blocks, threads>>>(logits, out,
                                                                n_tokens);
    }
}